// round 1
// baseline (speedup 1.0000x reference)
#include <cuda_runtime.h>

// ============================================================================
// ThermoQuantizer: out = (1-p)*x + p * mean_c * f(x/mean_c)
// where mean_c = max(group_abs_mean, 1e-5) and
// f(xn) = sum_i c_i * softmax_i(-(xn-c_i)^2 / T)
// Uniform codebook => softmax weights w_i ∝ E_i * r^i,
//   E_i = exp(-c_i^2/T),  r = exp(2*d*xn/T),  d = codebook spacing.
// => f = P_G(r)/P_E(r), two degree-15 polynomials with constant coefficients.
// One EX2 + 30 FFMA (15 packed f32x2) per element.
// ============================================================================

struct TQConsts {
    unsigned long long E2[16];   // (E_i, E_i) packed f32x2
    unsigned long long G2[16];   // (E_i*c_i, E_i*c_i) packed f32x2
    float Cexp2;                 // 2*d / (T*ln2): r = exp2(Cexp2 * xn)
    float p;                     // pressure
    float omp;                   // 1 - pressure
};
__device__ TQConsts g_tqc;

__global__ void tq_precompute(const float* __restrict__ cb,
                              const float* __restrict__ pressure,
                              const float* __restrict__ temp) {
    int i = threadIdx.x;
    double T = (double)(*temp) + 1e-6;
    if (i < 16) {
        double c = (double)cb[i];
        double E = exp(-(c * c) / T);
        float Ef = (float)E;
        float Gf = (float)(E * c);
        unsigned int eu = __float_as_uint(Ef);
        unsigned int gu = __float_as_uint(Gf);
        g_tqc.E2[i] = ((unsigned long long)eu << 32) | (unsigned long long)eu;
        g_tqc.G2[i] = ((unsigned long long)gu << 32) | (unsigned long long)gu;
    }
    if (i == 0) {
        double d = ((double)cb[15] - (double)cb[0]) / 15.0;
        g_tqc.Cexp2 = (float)(2.0 * d / (T * 0.693147180559945309417));
        float pf = *pressure;
        g_tqc.p = pf;
        g_tqc.omp = 1.0f - pf;
    }
}

// ---------------- packed f32x2 helpers ----------------
__device__ __forceinline__ unsigned long long f32x2_pack(float lo, float hi) {
    unsigned long long r;
    asm("mov.b64 %0, {%1, %2};" : "=l"(r) : "f"(lo), "f"(hi));
    return r;
}
__device__ __forceinline__ void f32x2_unpack(unsigned long long v, float& lo, float& hi) {
    asm("mov.b64 {%0, %1}, %2;" : "=f"(lo), "=f"(hi) : "l"(v));
}
__device__ __forceinline__ unsigned long long f32x2_fma(unsigned long long a,
                                                        unsigned long long b,
                                                        unsigned long long c) {
    unsigned long long d;
    asm("fma.rn.f32x2 %0, %1, %2, %3;" : "=l"(d) : "l"(a), "l"(b), "l"(c));
    return d;
}
__device__ __forceinline__ float ex2_approx(float x) {
    float r;
    asm("ex2.approx.f32 %0, %1;" : "=f"(r) : "f"(x));
    return r;
}
__device__ __forceinline__ float rcp_approx(float x) {
    float r;
    asm("rcp.approx.f32 %0, %1;" : "=f"(r) : "f"(x));
    return r;
}

// One warp per group of 128 elements; each lane owns one float4.
__global__ __launch_bounds__(256, 2)
void tq_main(const float4* __restrict__ x4, float4* __restrict__ out4, int ngroups) {
    int gid = blockIdx.x * 8 + (threadIdx.x >> 5);
    if (gid >= ngroups) return;
    int lane = threadIdx.x & 31;
    int idx = (gid << 5) + lane;

    float4 v = x4[idx];

    // group abs-mean via warp reduction
    float s = fabsf(v.x) + fabsf(v.y) + fabsf(v.z) + fabsf(v.w);
    s += __shfl_xor_sync(0xffffffffu, s, 16);
    s += __shfl_xor_sync(0xffffffffu, s, 8);
    s += __shfl_xor_sync(0xffffffffu, s, 4);
    s += __shfl_xor_sync(0xffffffffu, s, 2);
    s += __shfl_xor_sync(0xffffffffu, s, 1);
    float mean = fmaxf(s * (1.0f / 128.0f), 1e-5f);
    float inv_mean = rcp_approx(mean);

    const TQConsts& C = g_tqc;
    float ks  = C.Cexp2 * inv_mean;   // r = exp2(ks * x)
    float pm  = C.p * mean;           // p * mean_c (un-normalizes qx)
    float omp = C.omp;

    // per-element r = exp2(clamp(ks*x, -8, 8)); clamp keeps r^15 finite
    float t0 = fminf(fmaxf(v.x * ks, -8.0f), 8.0f);
    float t1 = fminf(fmaxf(v.y * ks, -8.0f), 8.0f);
    float t2 = fminf(fmaxf(v.z * ks, -8.0f), 8.0f);
    float t3 = fminf(fmaxf(v.w * ks, -8.0f), 8.0f);
    float r0 = ex2_approx(t0);
    float r1 = ex2_approx(t1);
    float r2 = ex2_approx(t2);
    float r3 = ex2_approx(t3);

    unsigned long long rA = f32x2_pack(r0, r1);
    unsigned long long rB = f32x2_pack(r2, r3);

    unsigned long long nA = C.G2[15], dA = C.E2[15];
    unsigned long long nB = nA,       dB = dA;
#pragma unroll
    for (int i = 14; i >= 0; --i) {
        unsigned long long g = C.G2[i];
        unsigned long long e = C.E2[i];
        nA = f32x2_fma(nA, rA, g);
        dA = f32x2_fma(dA, rA, e);
        nB = f32x2_fma(nB, rB, g);
        dB = f32x2_fma(dB, rB, e);
    }

    float n0, n1, n2, n3, d0, d1, d2, d3;
    f32x2_unpack(nA, n0, n1);
    f32x2_unpack(dA, d0, d1);
    f32x2_unpack(nB, n2, n3);
    f32x2_unpack(dB, d2, d3);

    float q0 = n0 * rcp_approx(d0);
    float q1 = n1 * rcp_approx(d1);
    float q2 = n2 * rcp_approx(d2);
    float q3 = n3 * rcp_approx(d3);

    float4 o;
    o.x = fmaf(pm, q0, omp * v.x);
    o.y = fmaf(pm, q1, omp * v.y);
    o.z = fmaf(pm, q2, omp * v.z);
    o.w = fmaf(pm, q3, omp * v.w);
    out4[idx] = o;
}

extern "C" void kernel_launch(void* const* d_in, const int* in_sizes, int n_in,
                              void* d_out, int out_size) {
    const float* x        = (const float*)d_in[0];
    const float* cb       = (const float*)d_in[1];
    const float* pressure = (const float*)d_in[2];
    const float* temp     = (const float*)d_in[3];

    int n = in_sizes[0];
    int ngroups = n / 128;            // groups of 128 contiguous elements
    int blocks = (ngroups + 7) / 8;   // 8 warps (groups) per block

    tq_precompute<<<1, 32>>>(cb, pressure, temp);
    tq_main<<<blocks, 256>>>((const float4*)x, (float4*)d_out, ngroups);
}

// round 2
// speedup vs baseline: 2.3216x; 2.3216x over previous
#include <cuda_runtime.h>
#include <math.h>

// ============================================================================
// ThermoQuantizer via 1-D lookup table.
//
// out = (1-p)*x + p * mean_c * f(x / mean_c)
//   mean_c = max(group_abs_mean, 1e-5)
//   f(xn)  = sum_i c_i * softmax_i( -(xn - c_i)^2 / (T + 1e-6) )
//
// f is a smooth scalar function of xn only (codebook/temp are fixed inputs),
// so a tiny precompute kernel tabulates (f(t_j), f(t_{j+1})-f(t_j)) on an
// 8192-point grid over xn in [-16, 16]; the main kernel does one smem
// lookup + linear interp per element. Interp error ~1e-5 abs << 1e-3 budget.
// ============================================================================

#define TBL_N      8192
#define TBL_LO    (-16.0f)
#define TBL_SCALE (256.0f)          // TBL_N / 32 entries per unit xn
#define TBL_OFF   (4096.0f)         // -TBL_LO * TBL_SCALE

__device__ float2 g_table[TBL_N];
__device__ float  g_p, g_omp;

// ---------------------------------------------------------------------------
// Precompute: exact softmax (max-shifted, fp32) on the grid. 8192 threads.
// Each thread computes f at grid points j and j+1 (value + forward delta).
// ---------------------------------------------------------------------------
__global__ void tq_precompute(const float* __restrict__ cb,
                              const float* __restrict__ pressure,
                              const float* __restrict__ temp) {
    int j = blockIdx.x * blockDim.x + threadIdx.x;
    if (j >= TBL_N) return;

    float T = *temp + 1e-6f;
    float invT = 1.0f / T;
    float c[16];
#pragma unroll
    for (int i = 0; i < 16; i++) c[i] = cb[i];

    float f[2];
#pragma unroll
    for (int k = 0; k < 2; k++) {
        float xn = -16.0f + (float)(j + k) * (32.0f / (float)TBL_N);
        // max-shifted softmax in fp32
        float m = -3.4e38f;
        float lg[16];
#pragma unroll
        for (int i = 0; i < 16; i++) {
            float d = xn - c[i];
            lg[i] = -(d * d) * invT;
            m = fmaxf(m, lg[i]);
        }
        float sw = 0.0f, sc = 0.0f;
#pragma unroll
        for (int i = 0; i < 16; i++) {
            float w = __expf(lg[i] - m);
            sw += w;
            sc += w * c[i];
        }
        f[k] = sc / sw;
    }
    g_table[j] = make_float2(f[0], f[1] - f[0]);
    if (j == 0) {
        float p = *pressure;
        g_p   = p;
        g_omp = 1.0f - p;
    }
}

__device__ __forceinline__ float rcp_approx(float x) {
    float r;
    asm("rcp.approx.f32 %0, %1;" : "=f"(r) : "f"(x));
    return r;
}

// ---------------------------------------------------------------------------
// Main kernel: grid-stride over groups. One warp per 128-element group
// (one float4 per lane). Table in shared memory.
// ---------------------------------------------------------------------------
__global__ __launch_bounds__(512, 3)
void tq_main(const float4* __restrict__ x4, float4* __restrict__ out4, int ngroups) {
    __shared__ float2 tbl[TBL_N];

    // cooperative table load (64 KB) via float4
    {
        const float4* src = (const float4*)g_table;
        float4*       dst = (float4*)tbl;
#pragma unroll
        for (int i = 0; i < TBL_N / 2 / 512; i++)
            dst[threadIdx.x + i * 512] = src[threadIdx.x + i * 512];
    }
    __syncthreads();

    float p   = g_p;
    float omp = g_omp;

    int lane   = threadIdx.x & 31;
    int warp_g = blockIdx.x * (512 / 32) + (threadIdx.x >> 5);
    int nwarps = gridDim.x * (512 / 32);

    for (int gid = warp_g; gid < ngroups; gid += nwarps) {
        int idx = (gid << 5) + lane;
        float4 v = x4[idx];

        // group abs-mean (128 elems) via warp reduction
        float s = fabsf(v.x) + fabsf(v.y) + fabsf(v.z) + fabsf(v.w);
        s += __shfl_xor_sync(0xffffffffu, s, 16);
        s += __shfl_xor_sync(0xffffffffu, s, 8);
        s += __shfl_xor_sync(0xffffffffu, s, 4);
        s += __shfl_xor_sync(0xffffffffu, s, 2);
        s += __shfl_xor_sync(0xffffffffu, s, 1);
        float mean = fmaxf(s * (1.0f / 128.0f), 1e-5f);
        float inv  = rcp_approx(mean);

        float ks = inv * TBL_SCALE;   // index = x * ks + TBL_OFF
        float pm = p * mean;          // un-normalize factor

        float4 o;
        {
            float u = fminf(fmaxf(fmaf(v.x, ks, TBL_OFF), 0.0f), (float)(TBL_N - 1));
            int jx = (int)u; float fr = u - (float)jx;
            float2 t = tbl[jx];
            o.x = fmaf(pm, fmaf(fr, t.y, t.x), omp * v.x);
        }
        {
            float u = fminf(fmaxf(fmaf(v.y, ks, TBL_OFF), 0.0f), (float)(TBL_N - 1));
            int jx = (int)u; float fr = u - (float)jx;
            float2 t = tbl[jx];
            o.y = fmaf(pm, fmaf(fr, t.y, t.x), omp * v.y);
        }
        {
            float u = fminf(fmaxf(fmaf(v.z, ks, TBL_OFF), 0.0f), (float)(TBL_N - 1));
            int jx = (int)u; float fr = u - (float)jx;
            float2 t = tbl[jx];
            o.z = fmaf(pm, fmaf(fr, t.y, t.x), omp * v.z);
        }
        {
            float u = fminf(fmaxf(fmaf(v.w, ks, TBL_OFF), 0.0f), (float)(TBL_N - 1));
            int jx = (int)u; float fr = u - (float)jx;
            float2 t = tbl[jx];
            o.w = fmaf(pm, fmaf(fr, t.y, t.x), omp * v.w);
        }
        out4[idx] = o;
    }
}

extern "C" void kernel_launch(void* const* d_in, const int* in_sizes, int n_in,
                              void* d_out, int out_size) {
    const float* x        = (const float*)d_in[0];
    const float* cb       = (const float*)d_in[1];
    const float* pressure = (const float*)d_in[2];
    const float* temp     = (const float*)d_in[3];

    int n = in_sizes[0];
    int ngroups = n / 128;

    tq_precompute<<<TBL_N / 256, 256>>>(cb, pressure, temp);

    int blocks = 148 * 3;   // grid-stride; ~3 blocks/SM resident (64KB smem each)
    tq_main<<<blocks, 512>>>((const float4*)x, (float4*)d_out, ngroups);
}